// round 4
// baseline (speedup 1.0000x reference)
#include <cuda_runtime.h>
#include <cuda_fp16.h>
#include <math.h>

// Problem constants (B=1, C=256, H=64, W=96, R=4)
#define Hh 64
#define Ww 96
#define Cc 256
#define HW (Hh * Ww)          // 6144
#define KK 9                  // 2R+1
#define NOUT (KK * KK)        // 81

// Pixel-major fp16 copy of fmap2: g_f2h[pixel][channel]
__device__ __half g_f2h[HW * Cc];

// --------------------------------------------------------------------------
// Tiled transpose + fp32->fp16 convert: [C, HW] -> [HW, C] (pixel-major half)
// --------------------------------------------------------------------------
__global__ __launch_bounds__(1024) void transpose_convert(const float* __restrict__ in) {
    __shared__ float tile[32][33];
    int p0 = blockIdx.x * 32;
    int c0 = blockIdx.y * 32;
    int tx = threadIdx.x, ty = threadIdx.y;
    tile[ty][tx] = in[(c0 + ty) * HW + (p0 + tx)];
    __syncthreads();
    g_f2h[(size_t)(p0 + ty) * Cc + (c0 + tx)] = __float2half(tile[tx][ty]);
}

// Accumulate 8 channels: one uint4 of halves vs two float4's of the query
#define ACC8(bu, Alo, Ahi, sA, sB) do {                                        \
    float2 q0 = __half22float2(*reinterpret_cast<const __half2*>(&(bu).x));    \
    float2 q1 = __half22float2(*reinterpret_cast<const __half2*>(&(bu).y));    \
    float2 q2 = __half22float2(*reinterpret_cast<const __half2*>(&(bu).z));    \
    float2 q3 = __half22float2(*reinterpret_cast<const __half2*>(&(bu).w));    \
    sA += (Alo).x*q0.x + (Alo).y*q0.y + (Alo).z*q1.x + (Alo).w*q1.y;           \
    sB += (Ahi).x*q2.x + (Ahi).y*q2.y + (Ahi).z*q3.x + (Ahi).w*q3.y;           \
} while (0)

// --------------------------------------------------------------------------
// Main kernel: one warp per query pixel (8 per 256-thread block).
// Phase 1: 50 passes; each pass computes 2 window columns with 16 lanes each.
//          Lane g = lane&15 owns channels {8g..8g+7} and {8(g+16)..}, so the
//          16 lanes of a column group read consecutive uint4s (coalesced).
//          Next pass's loads are prefetched (software pipeline, MLP=2+).
// Phase 2: 81 bilinear combines (i offsets x, j offsets y — meshgrid 'ij').
// Phase 3: coalesced store via padded shared staging.
// --------------------------------------------------------------------------
__global__ __launch_bounds__(256, 5) void corr_main(const float* __restrict__ coords,
                                                    const float* __restrict__ fmap1,
                                                    float* __restrict__ out) {
    __shared__ float f1s[8][Cc];        // per-query fp32 feature vectors
    __shared__ float win[8][11 * 12];   // per-warp corr windows (zero-guarded)
    __shared__ float sout[NOUT][9];     // padded output staging

    const int t = threadIdx.x;
    const int warp = t >> 5;
    const int lane = t & 31;
    const int q0 = blockIdx.x * 8;

    // ---- Phase 0: stage fmap1 rows (channel-major -> shared pixel-major)
    {
        const int i = t & 7;
        const int cb = t >> 3;
        #pragma unroll
        for (int c = cb; c < Cc; c += 32)
            f1s[i][c] = fmap1[c * HW + q0 + i];
    }
    __syncthreads();

    const int q = q0 + warp;
    const float cx = coords[q];          // channel 0 = x
    const float cy = coords[HW + q];     // channel 1 = y
    const int xb = (int)floorf(cx) - 4;
    const int yb = (int)floorf(cy) - 4;

    const int g = lane & 15;       // channel chunk
    const int colsel = lane >> 4;  // which of the 2 columns in this pass

    // This lane's 16 channels: 8g..8g+7 and 8(g+16)..8(g+16)+7
    float4 A0, A1, A2, A3;
    {
        const float4* rowf4 = reinterpret_cast<const float4*>(f1s[warp]);
        A0 = rowf4[2 * g];
        A1 = rowf4[2 * g + 1];
        A2 = rowf4[2 * g + 32];
        A3 = rowf4[2 * g + 33];
    }

    float* w = win[warp];
    #pragma unroll
    for (int i = lane; i < 11 * 12; i += 32) w[i] = 0.0f;
    __syncwarp();

    const uint4* f2 = reinterpret_cast<const uint4*>(g_f2h);

    // Clamped column base address for pass p (this lane's column)
    auto coladdr = [&](int p_) -> const uint4* {
        const int c  = 2 * p_ + colsel;
        const int iy = c / 10;
        const int jx = c - iy * 10;
        const int yc = min(max(yb + iy, 0), Hh - 1);
        const int xc = min(max(xb + jx, 0), Ww - 1);
        return f2 + (size_t)(yc * Ww + xc) * (Cc / 8) + g;
    };

    // ---- Phase 1: 10x10 window, 2 columns per pass, prefetched
    const uint4* addr = coladdr(0);
    uint4 b0 = addr[0];
    uint4 b1 = addr[16];

    #pragma unroll 1
    for (int p = 0; p < 50; ++p) {
        const uint4 c0 = b0, c1 = b1;
        if (p < 49) {
            addr = coladdr(p + 1);
            b0 = addr[0];
            b1 = addr[16];
        }

        const int c  = 2 * p + colsel;
        const int iy = c / 10;
        const int jx = c - iy * 10;
        const bool ok = ((unsigned)(yb + iy) < (unsigned)Hh)
                      & ((unsigned)(xb + jx) < (unsigned)Ww);

        float sA = 0.f, sB = 0.f;
        ACC8(c0, A0, A1, sA, sB);
        ACC8(c1, A2, A3, sA, sB);
        float s = sA + sB;
        s = ok ? s : 0.0f;

        // reduce across the 16 lanes of this column group
        s += __shfl_xor_sync(0xffffffffu, s, 1);
        s += __shfl_xor_sync(0xffffffffu, s, 2);
        s += __shfl_xor_sync(0xffffffffu, s, 4);
        s += __shfl_xor_sync(0xffffffffu, s, 8);
        if (g == 0) w[iy * 12 + jx] = s * 0.0625f;   // / sqrt(256)
    }
    __syncwarp();

    // ---- Phase 2: bilinear gather of the 81 outputs -> staged in shared
    #pragma unroll
    for (int k = lane; k < NOUT; k += 32) {
        const int i = k / KK;          // offsets the X coordinate
        const int j = k - i * KK;      // offsets the Y coordinate
        const float x = cx + (float)(i - 4);
        const float y = cy + (float)(j - 4);
        const float x0 = floorf(x);
        const float y0 = floorf(y);
        const int ix = (int)x0 - xb;   // 0..8 (exact fp32 integer adds)
        const int iw = (int)y0 - yb;   // 0..8
        const float wx1 = x - x0, wy1 = y - y0;
        const float wx0 = 1.0f - wx1, wy0 = 1.0f - wy1;
        const float* r0 = w + iw * 12 + ix;
        const float* r1 = r0 + 12;
        sout[k][warp] = wy0 * (wx0 * r0[0] + wx1 * r0[1])
                      + wy1 * (wx0 * r1[0] + wx1 * r1[1]);
    }
    __syncthreads();

    // ---- Phase 3: coalesced store (8 consecutive q per 32B sector)
    for (int e = t; e < NOUT * 8; e += 256) {
        const int k = e >> 3;
        const int i = e & 7;
        out[(size_t)k * HW + q0 + i] = sout[k][i];
    }
}

// --------------------------------------------------------------------------
extern "C" void kernel_launch(void* const* d_in, const int* in_sizes, int n_in,
                              void* d_out, int out_size) {
    const float* fmap1  = (const float*)d_in[0];
    const float* fmap2  = (const float*)d_in[1];
    const float* coords = (const float*)d_in[2];
    float* out = (float*)d_out;

    dim3 tb(32, 32);
    dim3 tg(HW / 32, Cc / 32);
    transpose_convert<<<tg, tb>>>(fmap2);
    corr_main<<<HW / 8, 256>>>(coords, fmap1, out);
}

// round 5
// speedup vs baseline: 1.6215x; 1.6215x over previous
#include <cuda_runtime.h>
#include <cuda_fp16.h>
#include <math.h>

// Problem constants (B=1, C=256, H=64, W=96, R=4)
#define Hh 64
#define Ww 96
#define Cc 256
#define HW (Hh * Ww)          // 6144
#define KK 9                  // 2R+1
#define NOUT (KK * KK)        // 81

// Pixel-major fp16 copy of fmap2: g_f2h[pixel][channel]
__device__ __half g_f2h[HW * Cc];

// --------------------------------------------------------------------------
// Tiled transpose + fp32->fp16 convert: [C, HW] -> [HW, C] (pixel-major half)
// --------------------------------------------------------------------------
__global__ __launch_bounds__(1024) void transpose_convert(const float* __restrict__ in) {
    __shared__ float tile[32][33];
    int p0 = blockIdx.x * 32;
    int c0 = blockIdx.y * 32;
    int tx = threadIdx.x, ty = threadIdx.y;
    tile[ty][tx] = in[(c0 + ty) * HW + (p0 + tx)];
    __syncthreads();
    g_f2h[(size_t)(p0 + ty) * Cc + (c0 + tx)] = __float2half(tile[tx][ty]);
}

// --------------------------------------------------------------------------
// Main kernel: one warp per query pixel (8 per 256-thread block).
// Phase 0:   stage fmap1 query vectors as half2 into shared.
// Phase 0.5: per-warp metadata table: 100 window columns -> {byte addr
//            (clamped), scale = ok ? 1/16 : 0}. All clamps/divs hoisted here.
// Phase 1:   25 passes; 4 columns/pass, 8 lanes/column, HFMA2 math,
//            next pass double-buffered (meta + 4x uint4).
// Phase 2:   81 bilinear combines (i offsets x, j offsets y — meshgrid 'ij').
// Phase 3:   coalesced store via padded shared staging.
// --------------------------------------------------------------------------
__global__ __launch_bounds__(256, 4) void corr_main(const float* __restrict__ coords,
                                                    const float* __restrict__ fmap1,
                                                    float* __restrict__ out) {
    __shared__ __half2 f1h[8][Cc / 2];   // 4 KB   query vectors (half2)
    __shared__ float win[8][11 * 12];    // 4.2 KB zero-guarded corr windows
    __shared__ float sout[NOUT][9];      // 2.9 KB padded output staging
    __shared__ uint2 meta[8][100];       // 6.4 KB {column byte addr, scale bits}

    const int t = threadIdx.x;
    const int warp = t >> 5;
    const int lane = t & 31;
    const int q0 = blockIdx.x * 8;

    // ---- Phase 0: fmap1 (channel-major fp32) -> shared half2, pixel-major
    {
        const int i = t & 7;         // query-in-block
        const int c2 = t >> 3;       // half2 index 0..31
        #pragma unroll
        for (int k = 0; k < 4; ++k) {
            const int cp = c2 + 32 * k;
            const float lo = fmap1[(2 * cp) * HW + q0 + i];
            const float hi = fmap1[(2 * cp + 1) * HW + q0 + i];
            f1h[i][cp] = __floats2half2_rn(lo, hi);
        }
    }
    __syncthreads();

    const int q = q0 + warp;
    const float cx = coords[q];          // channel 0 = x
    const float cy = coords[HW + q];     // channel 1 = y
    const int xb = (int)floorf(cx) - 4;
    const int yb = (int)floorf(cy) - 4;

    // ---- Phase 0.5: per-warp column metadata + window zero-init
    for (int c = lane; c < 100; c += 32) {
        const int iy = c / 10;
        const int jx = c - iy * 10;
        const int yy = yb + iy;
        const int xx = xb + jx;
        const bool ok = ((unsigned)yy < (unsigned)Hh) && ((unsigned)xx < (unsigned)Ww);
        const int yc = min(max(yy, 0), Hh - 1);
        const int xc = min(max(xx, 0), Ww - 1);
        uint2 m;
        m.x = (unsigned)((yc * Ww + xc) * (Cc * 2));   // column byte offset
        m.y = __float_as_uint(ok ? 0.0625f : 0.0f);    // / sqrt(256), OOB folded
        meta[warp][c] = m;
    }
    #pragma unroll
    for (int i = lane; i < 11 * 12; i += 32) win[warp][i] = 0.0f;
    __syncwarp();

    const int g = lane & 7;        // channel chunk within column
    const int colsel = lane >> 3;  // which of the 4 columns this pass

    // Lane's 32 channels of the query vector as 16 half2
    __half2 A[16];
    #pragma unroll
    for (int k = 0; k < 4; ++k)
        #pragma unroll
        for (int j = 0; j < 4; ++j)
            A[4 * k + j] = f1h[warp][4 * g + 32 * k + j];

    const char* f2base = (const char*)g_f2h + g * 16;   // lane's uint4 slot
    float* w = win[warp];

    // incremental (iy, jx) tracker for this lane's column: c = 4p + colsel
    int iy = 0, jx = colsel;

    // preload pass 0
    uint2 m = meta[warp][colsel];
    uint4 d0, d1, d2, d3;
    {
        const char* a = f2base + m.x;
        d0 = *(const uint4*)(a);
        d1 = *(const uint4*)(a + 128);
        d2 = *(const uint4*)(a + 256);
        d3 = *(const uint4*)(a + 384);
    }

    // ---- Phase 1: 10x10 window, 4 columns/pass, double-buffered
    #pragma unroll 1
    for (int p = 0; p < 25; ++p) {
        const uint4 c0 = d0, c1 = d1, c2 = d2, c3 = d3;
        const float scale = __uint_as_float(m.y);
        const int widx = iy * 12 + jx;

        if (p < 24) {
            m = meta[warp][4 * (p + 1) + colsel];
            const char* a = f2base + m.x;
            d0 = *(const uint4*)(a);
            d1 = *(const uint4*)(a + 128);
            d2 = *(const uint4*)(a + 256);
            d3 = *(const uint4*)(a + 384);
        }

        const __half2* b0 = reinterpret_cast<const __half2*>(&c0);
        const __half2* b1 = reinterpret_cast<const __half2*>(&c1);
        const __half2* b2 = reinterpret_cast<const __half2*>(&c2);
        const __half2* b3 = reinterpret_cast<const __half2*>(&c3);

        __half2 acc0 = __hmul2(b0[0], A[0]);
        __half2 acc1 = __hmul2(b0[1], A[1]);
        __half2 acc2 = __hmul2(b0[2], A[2]);
        __half2 acc3 = __hmul2(b0[3], A[3]);
        acc0 = __hfma2(b1[0], A[4],  acc0);
        acc1 = __hfma2(b1[1], A[5],  acc1);
        acc2 = __hfma2(b1[2], A[6],  acc2);
        acc3 = __hfma2(b1[3], A[7],  acc3);
        acc0 = __hfma2(b2[0], A[8],  acc0);
        acc1 = __hfma2(b2[1], A[9],  acc1);
        acc2 = __hfma2(b2[2], A[10], acc2);
        acc3 = __hfma2(b2[3], A[11], acc3);
        acc0 = __hfma2(b3[0], A[12], acc0);
        acc1 = __hfma2(b3[1], A[13], acc1);
        acc2 = __hfma2(b3[2], A[14], acc2);
        acc3 = __hfma2(b3[3], A[15], acc3);

        const __half2 t0 = __hadd2(acc0, acc1);
        const __half2 t1 = __hadd2(acc2, acc3);
        const float2 f2v = __half22float2(__hadd2(t0, t1));
        float s = f2v.x + f2v.y;

        // reduce across the 8 lanes of this column group
        s += __shfl_xor_sync(0xffffffffu, s, 1);
        s += __shfl_xor_sync(0xffffffffu, s, 2);
        s += __shfl_xor_sync(0xffffffffu, s, 4);
        if (g == 0) w[widx] = s * scale;

        // advance (iy, jx) by 4 columns (row length 10)
        jx += 4;
        if (jx >= 10) { jx -= 10; ++iy; }
    }
    __syncwarp();

    // ---- Phase 2: bilinear gather of the 81 outputs -> staged in shared
    #pragma unroll
    for (int k = lane; k < NOUT; k += 32) {
        const int i = k / KK;          // offsets the X coordinate
        const int j = k - i * KK;      // offsets the Y coordinate
        const float x = cx + (float)(i - 4);
        const float y = cy + (float)(j - 4);
        const float x0 = floorf(x);
        const float y0 = floorf(y);
        const int ix = (int)x0 - xb;   // 0..8 (exact fp32 integer adds)
        const int iw = (int)y0 - yb;   // 0..8
        const float wx1 = x - x0, wy1 = y - y0;
        const float wx0 = 1.0f - wx1, wy0 = 1.0f - wy1;
        const float* r0 = w + iw * 12 + ix;
        const float* r1 = r0 + 12;
        sout[k][warp] = wy0 * (wx0 * r0[0] + wx1 * r0[1])
                      + wy1 * (wx0 * r1[0] + wx1 * r1[1]);
    }
    __syncthreads();

    // ---- Phase 3: coalesced store (8 consecutive q per 32B sector)
    for (int e = t; e < NOUT * 8; e += 256) {
        const int k = e >> 3;
        const int i = e & 7;
        out[(size_t)k * HW + q0 + i] = sout[k][i];
    }
}

// --------------------------------------------------------------------------
extern "C" void kernel_launch(void* const* d_in, const int* in_sizes, int n_in,
                              void* d_out, int out_size) {
    const float* fmap1  = (const float*)d_in[0];
    const float* fmap2  = (const float*)d_in[1];
    const float* coords = (const float*)d_in[2];
    float* out = (float*)d_out;

    dim3 tb(32, 32);
    dim3 tg(HW / 32, Cc / 32);
    transpose_convert<<<tg, tb>>>(fmap2);
    corr_main<<<HW / 8, 256>>>(coords, fmap1, out);
}